// round 2
// baseline (speedup 1.0000x reference)
#include <cuda_runtime.h>
#include <cstdint>

// Compressor: per-8x8-block DCT-II (C = M^T B M), per-block inf-norm,
// int8-bin quantization (round-half-even), outputs indices + biggest.
//
// x: 8192x8192 fp32.  dct: 8x8 fp32, M[element][frequency].

static constexpr int W_DIM  = 8192;
static constexpr int BLK    = 8;
static constexpr float RADIUS = 127.0f;

// OUT_FLOAT=true : d_out = [float indices (n floats)][float biggest (nblocks floats)]
// OUT_FLOAT=false: d_out = [int8 indices (n bytes)][float biggest (nblocks floats)]
template <bool OUT_FLOAT>
__global__ __launch_bounds__(256, 3)
void dct_quant_kernel(const float* __restrict__ x,
                      const float* __restrict__ dct,
                      void* __restrict__ out_indices,
                      float* __restrict__ out_biggest,
                      int blocks_per_row)
{
    __shared__ float Ms[64];
    const int tid = threadIdx.x;
    if (tid < 64) Ms[tid] = dct[tid];
    __syncthreads();

    const int t  = blockIdx.x * blockDim.x + tid;
    const int b1 = t / blocks_per_row;
    const int b2 = t - b1 * blocks_per_row;

    // ---- Load 8x8 block, front-batched float4 streaming loads (MLP=16) ----
    const float* src = x + (size_t)(b1 * BLK) * W_DIM + (size_t)b2 * BLK;
    float A[8][8];   // single in-place array: B -> D -> C
#pragma unroll
    for (int e = 0; e < 8; e++) {
        const float4 v0 = __ldcs(reinterpret_cast<const float4*>(src + (size_t)e * W_DIM));
        const float4 v1 = __ldcs(reinterpret_cast<const float4*>(src + (size_t)e * W_DIM + 4));
        A[e][0] = v0.x; A[e][1] = v0.y; A[e][2] = v0.z; A[e][3] = v0.w;
        A[e][4] = v1.x; A[e][5] = v1.y; A[e][6] = v1.z; A[e][7] = v1.w;
    }

    // ---- Stage 1 (in-place, column-wise): A[:,f] := M^T * A[:,f]
    //      D[g][f] = sum_e M[e][g] * B[e][f]
#pragma unroll
    for (int f = 0; f < 8; f++) {
        float col[8];
#pragma unroll
        for (int g = 0; g < 8; g++) col[g] = 0.0f;
#pragma unroll
        for (int e = 0; e < 8; e++) {
            const float b = A[e][f];
#pragma unroll
            for (int g = 0; g < 8; g++)
                col[g] = fmaf(Ms[e * 8 + g], b, col[g]);
        }
#pragma unroll
        for (int g = 0; g < 8; g++) A[g][f] = col[g];
    }

    // ---- Stage 2 (in-place, row-wise): A[g,:] := A[g,:] * M
    //      C[g][h] = sum_f D[g][f] * M[f][h];  track inf-norm
    float maxv = 0.0f;
#pragma unroll
    for (int g = 0; g < 8; g++) {
        float row[8];
#pragma unroll
        for (int h = 0; h < 8; h++) row[h] = 0.0f;
#pragma unroll
        for (int f = 0; f < 8; f++) {
            const float d = A[g][f];
#pragma unroll
            for (int h = 0; h < 8; h++)
                row[h] = fmaf(d, Ms[f * 8 + h], row[h]);
        }
#pragma unroll
        for (int h = 0; h < 8; h++) {
            A[g][h] = row[h];
            maxv = fmaxf(maxv, fabsf(row[h]));
        }
    }

    const float scale = RADIUS / maxv;

    if (OUT_FLOAT) {
        float* outp = reinterpret_cast<float*>(out_indices) + (size_t)t * 64;
#pragma unroll
        for (int g = 0; g < 8; g++) {
            float4 w0, w1;
            w0.x = (float)__float2int_rn(A[g][0] * scale);
            w0.y = (float)__float2int_rn(A[g][1] * scale);
            w0.z = (float)__float2int_rn(A[g][2] * scale);
            w0.w = (float)__float2int_rn(A[g][3] * scale);
            w1.x = (float)__float2int_rn(A[g][4] * scale);
            w1.y = (float)__float2int_rn(A[g][5] * scale);
            w1.z = (float)__float2int_rn(A[g][6] * scale);
            w1.w = (float)__float2int_rn(A[g][7] * scale);
            __stcs(reinterpret_cast<float4*>(outp + g * 8) + 0, w0);
            __stcs(reinterpret_cast<float4*>(outp + g * 8) + 1, w1);
        }
    } else {
        uint32_t words[16];
#pragma unroll
        for (int i = 0; i < 16; i++) {
            const int g = i >> 1;
            const int hb = (i & 1) * 4;
            uint32_t w = 0;
#pragma unroll
            for (int j = 0; j < 4; j++) {
                const int q = __float2int_rn(A[g][hb + j] * scale);
                w |= (uint32_t)(q & 0xFF) << (8 * j);
            }
            words[i] = w;
        }
        uint4* outp = reinterpret_cast<uint4*>(
            reinterpret_cast<int8_t*>(out_indices) + (size_t)t * 64);
#pragma unroll
        for (int i = 0; i < 4; i++)
            __stcs(outp + i, make_uint4(words[4*i], words[4*i+1], words[4*i+2], words[4*i+3]));
    }

    __stcs(out_biggest + t, maxv);
}

extern "C" void kernel_launch(void* const* d_in, const int* in_sizes, int n_in,
                              void* d_out, int out_size)
{
    const float* x   = (const float*)d_in[0];
    const float* dct = (const float*)d_in[1];

    const int n        = in_sizes[0];          // 67108864
    const int nblocks  = n / 64;               // 1048576
    const int bpr      = W_DIM / BLK;          // 1024
    const int threads  = 256;
    const int grid     = nblocks / threads;    // 4096

    if (out_size == n + nblocks) {
        float* outF = (float*)d_out;
        dct_quant_kernel<true><<<grid, threads>>>(x, dct, (void*)outF, outF + n, bpr);
    } else {
        int8_t* idx = (int8_t*)d_out;
        float*  big = (float*)((char*)d_out + (size_t)n);
        dct_quant_kernel<false><<<grid, threads>>>(x, dct, (void*)idx, big, bpr);
    }
}

// round 3
// speedup vs baseline: 1.1195x; 1.1195x over previous
#include <cuda_runtime.h>
#include <cstdint>

// Compressor: per-8x8-block DCT-II (C = M^T B M), per-block inf-norm,
// int8-bin quantization (round-half-even), outputs indices + biggest.
// x: 8192x8192 fp32.  dct: 8x8 fp32, M[element][frequency].

static constexpr int W_DIM  = 8192;
static constexpr int BLK    = 8;
static constexpr float RADIUS = 127.0f;
static constexpr int CTA    = 128;      // 4 warps
static constexpr int WARPS  = CTA / 32;

// OUT_FLOAT=true : d_out = [float indices (n floats)][float biggest (nblocks floats)]
// OUT_FLOAT=false: d_out = [int8 indices (n bytes)][float biggest (nblocks floats)]
template <bool OUT_FLOAT>
__global__ __launch_bounds__(CTA, 6)
void dct_quant_kernel(const float* __restrict__ x,
                      const float* __restrict__ dct,
                      void* __restrict__ out_indices,
                      float* __restrict__ out_biggest,
                      int blocks_per_row)
{
    __shared__ float Ms[64];
    __shared__ float4 stage[WARPS * 512];   // 8KB per warp = 32KB

    const int tid  = threadIdx.x;
    const int lane = tid & 31;
    const int wid  = tid >> 5;
    if (tid < 64) Ms[tid] = dct[tid];
    __syncthreads();

    const int t  = blockIdx.x * CTA + tid;
    const int b1 = t / blocks_per_row;
    const int b2 = t - b1 * blocks_per_row;

    // ---- Load 8x8 block, front-batched float4 streaming loads (MLP=16) ----
    const float* src = x + (size_t)(b1 * BLK) * W_DIM + (size_t)b2 * BLK;
    float A[8][8];   // in-place: B -> D -> C
#pragma unroll
    for (int e = 0; e < 8; e++) {
        const float4 v0 = __ldcs(reinterpret_cast<const float4*>(src + (size_t)e * W_DIM));
        const float4 v1 = __ldcs(reinterpret_cast<const float4*>(src + (size_t)e * W_DIM + 4));
        A[e][0] = v0.x; A[e][1] = v0.y; A[e][2] = v0.z; A[e][3] = v0.w;
        A[e][4] = v1.x; A[e][5] = v1.y; A[e][6] = v1.z; A[e][7] = v1.w;
    }

    // ---- Stage 1 (in-place, column-wise): D[g][f] = sum_e M[e][g] * B[e][f] ----
#pragma unroll
    for (int f = 0; f < 8; f++) {
        float col[8];
#pragma unroll
        for (int g = 0; g < 8; g++) col[g] = 0.0f;
#pragma unroll
        for (int e = 0; e < 8; e++) {
            const float b = A[e][f];
#pragma unroll
            for (int g = 0; g < 8; g++)
                col[g] = fmaf(Ms[e * 8 + g], b, col[g]);
        }
#pragma unroll
        for (int g = 0; g < 8; g++) A[g][f] = col[g];
    }

    // ---- Stage 2 (in-place, row-wise): C[g][h] = sum_f D[g][f] * M[f][h]; inf-norm ----
    float maxv = 0.0f;
#pragma unroll
    for (int g = 0; g < 8; g++) {
        float row[8];
#pragma unroll
        for (int h = 0; h < 8; h++) row[h] = 0.0f;
#pragma unroll
        for (int f = 0; f < 8; f++) {
            const float d = A[g][f];
#pragma unroll
            for (int h = 0; h < 8; h++)
                row[h] = fmaf(d, Ms[f * 8 + h], row[h]);
        }
#pragma unroll
        for (int h = 0; h < 8; h++) {
            A[g][h] = row[h];
            maxv = fmaxf(maxv, fabsf(row[h]));
        }
    }

    const float scale = RADIUS / maxv;

    if (OUT_FLOAT) {
        // Quantize into per-warp SMEM staging buffer (swizzled: 4-way min conflicts),
        // then emit dense 8KB contiguous warp stores (4 lines per STG.128).
        float4* wbuf = stage + wid * 512;
#pragma unroll
        for (int j = 0; j < 16; j++) {
            const int g  = j >> 1;
            const int hb = (j & 1) * 4;
            float4 v;
            v.x = (float)__float2int_rn(A[g][hb + 0] * scale);
            v.y = (float)__float2int_rn(A[g][hb + 1] * scale);
            v.z = (float)__float2int_rn(A[g][hb + 2] * scale);
            v.w = (float)__float2int_rn(A[g][hb + 3] * scale);
            wbuf[lane * 16 + (j ^ (lane & 7))] = v;
        }
        __syncwarp();

        const int warp_first_block = blockIdx.x * CTA + wid * 32;
        float4* gout = reinterpret_cast<float4*>(
            reinterpret_cast<float*>(out_indices) + (size_t)warp_first_block * 64);
#pragma unroll
        for (int k = 0; k < 16; k++) {
            const int m    = k * 32 + lane;        // logical float4 index in warp region
            const int tsrc = m >> 4;               // source lane
            const int j    = m & 15;               // source j
            const float4 v = wbuf[tsrc * 16 + (j ^ (tsrc & 7))];
            __stcs(gout + m, v);
        }
    } else {
        // int8 fallback path (byte-packed layout)
        uint32_t words[16];
#pragma unroll
        for (int i = 0; i < 16; i++) {
            const int g = i >> 1;
            const int hb = (i & 1) * 4;
            uint32_t w = 0;
#pragma unroll
            for (int j = 0; j < 4; j++) {
                const int q = __float2int_rn(A[g][hb + j] * scale);
                w |= (uint32_t)(q & 0xFF) << (8 * j);
            }
            words[i] = w;
        }
        uint4* outp = reinterpret_cast<uint4*>(
            reinterpret_cast<int8_t*>(out_indices) + (size_t)t * 64);
#pragma unroll
        for (int i = 0; i < 4; i++)
            __stcs(outp + i, make_uint4(words[4*i], words[4*i+1], words[4*i+2], words[4*i+3]));
    }

    __stcs(out_biggest + t, maxv);
}

extern "C" void kernel_launch(void* const* d_in, const int* in_sizes, int n_in,
                              void* d_out, int out_size)
{
    const float* x   = (const float*)d_in[0];
    const float* dct = (const float*)d_in[1];

    const int n        = in_sizes[0];          // 67108864
    const int nblocks  = n / 64;               // 1048576
    const int bpr      = W_DIM / BLK;          // 1024
    const int grid     = nblocks / CTA;        // 8192

    if (out_size == n + nblocks) {
        float* outF = (float*)d_out;
        dct_quant_kernel<true><<<grid, CTA>>>(x, dct, (void*)outF, outF + n, bpr);
    } else {
        int8_t* idx = (int8_t*)d_out;
        float*  big = (float*)((char*)d_out + (size_t)n);
        dct_quant_kernel<false><<<grid, CTA>>>(x, dct, (void*)idx, big, bpr);
    }
}